// round 1
// baseline (speedup 1.0000x reference)
#include <cuda_runtime.h>

#define EPS 1e-8f

// Scratch (fixed problem shape: B=8192, D=4096)
__device__ float g_mask0[8192];
__device__ float g_rowss[8192];
__device__ float g_msum[4096];
__device__ float g_scale;   // 1 / (max(n0,1) * m_norm)
__device__ float g_n0f, g_n1f;
__device__ float g_sim, g_dif;

__device__ __forceinline__ float warpReduce(float v) {
    #pragma unroll
    for (int o = 16; o > 0; o >>= 1) v += __shfl_down_sync(0xffffffffu, v, o);
    return v;
}

// Kernel 1: masks + zero accumulators (re-zeroed every graph replay)
__global__ void k_init(const float* __restrict__ labels, int B, int D) {
    int i = blockIdx.x * blockDim.x + threadIdx.x;
    if (i == 0) { g_sim = 0.f; g_dif = 0.f; }
    if (i < D) g_msum[i] = 0.f;
    if (i < B) {
        float a = labels[2 * i];
        float b = labels[2 * i + 1];
        // jnp.argmax over C=2: label 1 only if labels[1] > labels[0]
        g_mask0[i] = (b > a) ? 0.f : 1.f;
    }
}

// Kernel 2: one streaming pass — masked column sums + per-row sum of squares.
// Requires D == 4096, blockDim == 256.
__global__ void __launch_bounds__(256) k_pass1(const float* __restrict__ datas,
                                               int D, int rowsPerBlock) {
    const int tid  = threadIdx.x;
    const int lane = tid & 31, wid = tid >> 5;
    __shared__ float sw[8];

    float csum[16];
    #pragma unroll
    for (int i = 0; i < 16; i++) csum[i] = 0.f;

    const int row0 = blockIdx.x * rowsPerBlock;
    for (int r = 0; r < rowsPerBlock; r++) {
        const int row = row0 + r;
        const float m = g_mask0[row];
        const float4* p = reinterpret_cast<const float4*>(datas + (size_t)row * D);
        float ss = 0.f;
        #pragma unroll
        for (int g = 0; g < 4; g++) {
            float4 v = p[tid + g * 256];
            ss += v.x * v.x + v.y * v.y + v.z * v.z + v.w * v.w;
            csum[4 * g + 0] += m * v.x;
            csum[4 * g + 1] += m * v.y;
            csum[4 * g + 2] += m * v.z;
            csum[4 * g + 3] += m * v.w;
        }
        ss = warpReduce(ss);
        if (lane == 0) sw[wid] = ss;
        __syncthreads();
        if (tid < 8) {
            float s = sw[tid];
            #pragma unroll
            for (int o = 4; o > 0; o >>= 1) s += __shfl_down_sync(0xffu, s, o);
            if (tid == 0) g_rowss[row] = s;
        }
        __syncthreads();
    }

    // One atomic per (thread, column) -> 256 contenders per address. Cheap.
    #pragma unroll
    for (int g = 0; g < 4; g++) {
        int j = tid + g * 256;
        atomicAdd(&g_msum[4 * j + 0], csum[4 * g + 0]);
        atomicAdd(&g_msum[4 * j + 1], csum[4 * g + 1]);
        atomicAdd(&g_msum[4 * j + 2], csum[4 * g + 2]);
        atomicAdd(&g_msum[4 * j + 3], csum[4 * g + 3]);
    }
}

// Kernel 3: tiny reductions — n0, ||mean_sum||, fused cosine scale.
__global__ void k_msum(int B, int D) {
    const int tid = threadIdx.x;
    const int lane = tid & 31, wid = tid >> 5;
    float n0 = 0.f, msq = 0.f;
    for (int i = tid; i < B; i += 256) n0 += g_mask0[i];
    for (int i = tid; i < D; i += 256) { float v = g_msum[i]; msq += v * v; }
    n0 = warpReduce(n0);
    msq = warpReduce(msq);
    __shared__ float s0[8], s1[8];
    if (lane == 0) { s0[wid] = n0; s1[wid] = msq; }
    __syncthreads();
    if (tid == 0) {
        float a = 0.f, b = 0.f;
        #pragma unroll
        for (int i = 0; i < 8; i++) { a += s0[i]; b += s1[i]; }
        float n0max = fmaxf(a, 1.f);
        // mean_vec = msum / n0max; m_norm = max(||mean_vec||, EPS)
        float mnorm = fmaxf(sqrtf(b) / n0max, EPS);
        g_scale = 1.f / (n0max * mnorm);
        g_n0f = a;
        g_n1f = (float)B - a;
    }
}

// Kernel 4: second streaming pass — dot(row, mean_sum) via smem-staged mean,
// per-row cosine losses accumulated per-block. Requires D == 4096.
__global__ void __launch_bounds__(256) k_pass2(const float* __restrict__ datas,
                                               int D, int rowsPerBlock) {
    const int tid  = threadIdx.x;
    const int lane = tid & 31, wid = tid >> 5;
    __shared__ float sm[4096];
    __shared__ float sw[8];
    for (int i = tid; i < D; i += 256) sm[i] = g_msum[i];
    __syncthreads();
    const float4* sm4 = reinterpret_cast<const float4*>(sm);

    const float scale = g_scale;
    float simacc = 0.f, difacc = 0.f;
    const int row0 = blockIdx.x * rowsPerBlock;
    for (int r = 0; r < rowsPerBlock; r++) {
        const int row = row0 + r;
        const float4* p = reinterpret_cast<const float4*>(datas + (size_t)row * D);
        float dot = 0.f;
        #pragma unroll
        for (int g = 0; g < 4; g++) {
            float4 v = p[tid + g * 256];
            float4 w = sm4[tid + g * 256];
            dot += v.x * w.x + v.y * w.y + v.z * w.z + v.w * w.w;
        }
        dot = warpReduce(dot);
        if (lane == 0) sw[wid] = dot;
        __syncthreads();
        if (tid == 0) {
            float s = 0.f;
            #pragma unroll
            for (int i = 0; i < 8; i++) s += sw[i];
            float xn = fmaxf(sqrtf(g_rowss[row]), EPS);
            // cos = (d . mean_vec) / (xn * m_norm) = dot * scale / xn
            float ac = fabsf(s * scale / xn);
            float m0 = g_mask0[row];
            simacc += m0 * (1.f - ac);
            difacc += (1.f - m0) * ac;
        }
        __syncthreads();
    }
    if (tid == 0) {
        atomicAdd(&g_sim, simacc);
        atomicAdd(&g_dif, difacc);
    }
}

// Kernel 5: finalize with reference's edge-case guards.
__global__ void k_final(float* __restrict__ out) {
    if (threadIdx.x == 0) {
        float n0 = g_n0f, n1 = g_n1f;
        float sim = (n0 > 0.f) ? g_sim / fmaxf(n0, 1.f) : 0.f;
        float dif = (n0 > 0.f && n1 > 0.f) ? g_dif / fmaxf(n1, 1.f) : 0.f;
        out[0] = sim + dif;  // total_loss
        out[1] = sim;        // sim_loss
        out[2] = dif;        // differ_loss
    }
}

extern "C" void kernel_launch(void* const* d_in, const int* in_sizes, int n_in,
                              void* d_out, int out_size) {
    // Identify labels (smaller tensor) vs datas robustly by size.
    const float* labels = (const float*)d_in[0];
    const float* datas  = (const float*)d_in[1];
    int ls = in_sizes[0], ds = in_sizes[1];
    if (n_in >= 2 && in_sizes[0] > in_sizes[1]) {
        labels = (const float*)d_in[1];
        datas  = (const float*)d_in[0];
        ls = in_sizes[1]; ds = in_sizes[0];
    }
    const int B = ls / 2;         // 8192
    const int D = ds / B;         // 4096
    const int NBLK = 256;
    const int R = B / NBLK;       // 32 rows per block

    k_init<<<(B + 255) / 256, 256>>>(labels, B, D);
    k_pass1<<<NBLK, 256>>>(datas, D, R);
    k_msum<<<1, 256>>>(B, D);
    k_pass2<<<NBLK, 256>>>(datas, D, R);
    k_final<<<1, 32>>>((float*)d_out);
}

// round 2
// speedup vs baseline: 2.2586x; 2.2586x over previous
#include <cuda_runtime.h>

#define EPS 1e-8f
#define B_SZ 8192
#define D_SZ 4096

// Scratch (fixed problem shape: B=8192, D=4096)
__device__ float g_mask0[B_SZ];
__device__ float g_msum[D_SZ];
__device__ float g_scale;   // 1 / (max(n0,1) * m_norm)
__device__ float g_n0f, g_n1f;
__device__ float g_sim, g_dif;

__device__ __forceinline__ float warpReduce(float v) {
    #pragma unroll
    for (int o = 16; o > 0; o >>= 1) v += __shfl_down_sync(0xffffffffu, v, o);
    return v;
}

// Kernel 1: masks + zero accumulators (re-zeroed every graph replay)
__global__ void k_init(const float* __restrict__ labels) {
    int i = blockIdx.x * blockDim.x + threadIdx.x;
    if (i == 0) { g_sim = 0.f; g_dif = 0.f; }
    if (i < D_SZ) g_msum[i] = 0.f;
    if (i < B_SZ) {
        float a = labels[2 * i];
        float b = labels[2 * i + 1];
        // jnp.argmax over C=2: label 1 only if labels[1] > labels[0]
        g_mask0[i] = (b > a) ? 0.f : 1.f;
    }
}

// Kernel 2: pure masked column sums. No barriers.
// Grid: 4 column tiles (1024 floats each) x 128 row groups (64 rows) = 512 blocks.
#define ROWS1 64
__global__ void __launch_bounds__(256) k_pass1(const float* __restrict__ datas) {
    const int tid     = threadIdx.x;
    const int colTile = blockIdx.x & 3;
    const int rowGrp  = blockIdx.x >> 2;
    const int col4    = colTile * 256 + tid;       // float4 column index
    const int row0    = rowGrp * ROWS1;

    const float4* base = reinterpret_cast<const float4*>(datas) + col4;

    float4 a0 = {0,0,0,0}, a1 = {0,0,0,0}, a2 = {0,0,0,0}, a3 = {0,0,0,0};
    #pragma unroll 4
    for (int r = 0; r < ROWS1; r += 4) {
        const float m0 = g_mask0[row0 + r + 0];
        const float m1 = g_mask0[row0 + r + 1];
        const float m2 = g_mask0[row0 + r + 2];
        const float m3 = g_mask0[row0 + r + 3];
        float4 v0 = base[(size_t)(row0 + r + 0) * (D_SZ / 4)];
        float4 v1 = base[(size_t)(row0 + r + 1) * (D_SZ / 4)];
        float4 v2 = base[(size_t)(row0 + r + 2) * (D_SZ / 4)];
        float4 v3 = base[(size_t)(row0 + r + 3) * (D_SZ / 4)];
        a0.x += m0 * v0.x; a0.y += m0 * v0.y; a0.z += m0 * v0.z; a0.w += m0 * v0.w;
        a1.x += m1 * v1.x; a1.y += m1 * v1.y; a1.z += m1 * v1.z; a1.w += m1 * v1.w;
        a2.x += m2 * v2.x; a2.y += m2 * v2.y; a2.z += m2 * v2.z; a2.w += m2 * v2.w;
        a3.x += m3 * v3.x; a3.y += m3 * v3.y; a3.z += m3 * v3.z; a3.w += m3 * v3.w;
    }
    float sx = (a0.x + a1.x) + (a2.x + a3.x);
    float sy = (a0.y + a1.y) + (a2.y + a3.y);
    float sz = (a0.z + a1.z) + (a2.z + a3.z);
    float sw = (a0.w + a1.w) + (a2.w + a3.w);
    atomicAdd(&g_msum[4 * col4 + 0], sx);
    atomicAdd(&g_msum[4 * col4 + 1], sy);
    atomicAdd(&g_msum[4 * col4 + 2], sz);
    atomicAdd(&g_msum[4 * col4 + 3], sw);
}

// Kernel 3: tiny reductions — n0, ||mean_sum||, fused cosine scale.
__global__ void k_msum() {
    const int tid = threadIdx.x;
    const int lane = tid & 31, wid = tid >> 5;
    float n0 = 0.f, msq = 0.f;
    for (int i = tid; i < B_SZ; i += 256) n0 += g_mask0[i];
    for (int i = tid; i < D_SZ; i += 256) { float v = g_msum[i]; msq += v * v; }
    n0 = warpReduce(n0);
    msq = warpReduce(msq);
    __shared__ float s0[8], s1[8];
    if (lane == 0) { s0[wid] = n0; s1[wid] = msq; }
    __syncthreads();
    if (tid == 0) {
        float a = 0.f, b = 0.f;
        #pragma unroll
        for (int i = 0; i < 8; i++) { a += s0[i]; b += s1[i]; }
        float n0max = fmaxf(a, 1.f);
        // mean_vec = msum / n0max; m_norm = max(||mean_vec||, EPS)
        float mnorm = fmaxf(sqrtf(b) / n0max, EPS);
        g_scale = 1.f / (n0max * mnorm);
        g_n0f = a;
        g_n1f = (float)B_SZ - a;
    }
}

// Kernel 4: warp-per-row — dot(row, mean_sum) AND row sum-of-squares in one
// pass, mean staged in smem. 1024 blocks x 8 warps = one warp per row.
__global__ void __launch_bounds__(256) k_pass2(const float* __restrict__ datas) {
    const int tid  = threadIdx.x;
    const int lane = tid & 31, wid = tid >> 5;
    __shared__ float4 sm4[D_SZ / 4];
    __shared__ float ssim[8], sdif[8];
    {
        const float4* gm4 = reinterpret_cast<const float4*>(g_msum);
        for (int i = tid; i < D_SZ / 4; i += 256) sm4[i] = gm4[i];
    }
    __syncthreads();

    const int row = blockIdx.x * 8 + wid;
    const float4* p = reinterpret_cast<const float4*>(datas + (size_t)row * D_SZ);

    float dot = 0.f, ss = 0.f;
    #pragma unroll 8
    for (int i = 0; i < D_SZ / 4 / 32; i++) {
        float4 v = p[lane + 32 * i];
        float4 w = sm4[lane + 32 * i];
        dot += v.x * w.x + v.y * w.y + v.z * w.z + v.w * w.w;
        ss  += v.x * v.x + v.y * v.y + v.z * v.z + v.w * v.w;
    }
    dot = warpReduce(dot);
    ss  = warpReduce(ss);

    if (lane == 0) {
        float xn = fmaxf(sqrtf(ss), EPS);
        // cos = (d . mean_vec) / (xn * m_norm) = dot * g_scale / xn
        float ac = fabsf(dot * g_scale / xn);
        float m0 = g_mask0[row];
        ssim[wid] = m0 * (1.f - ac);
        sdif[wid] = (1.f - m0) * ac;
    }
    __syncthreads();
    if (tid == 0) {
        float a = 0.f, b = 0.f;
        #pragma unroll
        for (int i = 0; i < 8; i++) { a += ssim[i]; b += sdif[i]; }
        atomicAdd(&g_sim, a);
        atomicAdd(&g_dif, b);
    }
}

// Kernel 5: finalize with reference's edge-case guards.
__global__ void k_final(float* __restrict__ out) {
    if (threadIdx.x == 0) {
        float n0 = g_n0f, n1 = g_n1f;
        float sim = (n0 > 0.f) ? g_sim / fmaxf(n0, 1.f) : 0.f;
        float dif = (n0 > 0.f && n1 > 0.f) ? g_dif / fmaxf(n1, 1.f) : 0.f;
        out[0] = sim + dif;  // total_loss
        out[1] = sim;        // sim_loss
        out[2] = dif;        // differ_loss
    }
}

extern "C" void kernel_launch(void* const* d_in, const int* in_sizes, int n_in,
                              void* d_out, int out_size) {
    // Identify labels (smaller tensor) vs datas by size.
    const float* labels = (const float*)d_in[0];
    const float* datas  = (const float*)d_in[1];
    if (n_in >= 2 && in_sizes[0] > in_sizes[1]) {
        labels = (const float*)d_in[1];
        datas  = (const float*)d_in[0];
    }

    k_init<<<(B_SZ + 255) / 256, 256>>>(labels);
    k_pass1<<<4 * (B_SZ / ROWS1), 256>>>(datas);   // 512 blocks
    k_msum<<<1, 256>>>();
    k_pass2<<<B_SZ / 8, 256>>>(datas);             // 1024 blocks
    k_final<<<1, 32>>>((float*)d_out);
}

// round 3
// speedup vs baseline: 2.2712x; 1.0056x over previous
#include <cuda_runtime.h>

#define EPS 1e-8f
#define B_SZ 8192
#define D_SZ 4096

// Scratch. Zero-initialized at module load; k_final restores zeros each replay.
__device__ float g_msum[D_SZ];
__device__ float g_scale;   // 1 / (max(n0,1) * m_norm)
__device__ float g_n0f, g_n1f;
__device__ float g_sim, g_dif;

__device__ __forceinline__ float warpReduce(float v) {
    #pragma unroll
    for (int o = 16; o > 0; o >>= 1) v += __shfl_down_sync(0xffffffffu, v, o);
    return v;
}

__device__ __forceinline__ float mask0_of(const float* __restrict__ labels, int row) {
    // jnp.argmax over C=2: label 1 only if labels[1] > labels[0]
    return (labels[2 * row + 1] > labels[2 * row]) ? 0.f : 1.f;
}

// Pass 1: masked column sums, FORWARD row order. No barriers.
// Grid: 4 column tiles x 128 row groups (64 rows) = 512 blocks.
#define ROWS1 64
__global__ void __launch_bounds__(256) k_pass1(const float* __restrict__ datas,
                                               const float* __restrict__ labels) {
    const int tid     = threadIdx.x;
    const int colTile = blockIdx.x & 3;
    const int rowGrp  = blockIdx.x >> 2;
    const int col4    = colTile * 256 + tid;       // float4 column index
    const int row0    = rowGrp * ROWS1;

    const float4* base = reinterpret_cast<const float4*>(datas) + col4;

    float4 a0 = {0,0,0,0}, a1 = {0,0,0,0}, a2 = {0,0,0,0}, a3 = {0,0,0,0};
    #pragma unroll 4
    for (int r = 0; r < ROWS1; r += 4) {
        const float m0 = mask0_of(labels, row0 + r + 0);
        const float m1 = mask0_of(labels, row0 + r + 1);
        const float m2 = mask0_of(labels, row0 + r + 2);
        const float m3 = mask0_of(labels, row0 + r + 3);
        float4 v0 = base[(size_t)(row0 + r + 0) * (D_SZ / 4)];
        float4 v1 = base[(size_t)(row0 + r + 1) * (D_SZ / 4)];
        float4 v2 = base[(size_t)(row0 + r + 2) * (D_SZ / 4)];
        float4 v3 = base[(size_t)(row0 + r + 3) * (D_SZ / 4)];
        a0.x += m0 * v0.x; a0.y += m0 * v0.y; a0.z += m0 * v0.z; a0.w += m0 * v0.w;
        a1.x += m1 * v1.x; a1.y += m1 * v1.y; a1.z += m1 * v1.z; a1.w += m1 * v1.w;
        a2.x += m2 * v2.x; a2.y += m2 * v2.y; a2.z += m2 * v2.z; a2.w += m2 * v2.w;
        a3.x += m3 * v3.x; a3.y += m3 * v3.y; a3.z += m3 * v3.z; a3.w += m3 * v3.w;
    }
    atomicAdd(&g_msum[4 * col4 + 0], (a0.x + a1.x) + (a2.x + a3.x));
    atomicAdd(&g_msum[4 * col4 + 1], (a0.y + a1.y) + (a2.y + a3.y));
    atomicAdd(&g_msum[4 * col4 + 2], (a0.z + a1.z) + (a2.z + a3.z));
    atomicAdd(&g_msum[4 * col4 + 3], (a0.w + a1.w) + (a2.w + a3.w));
}

// Tiny reductions: n0 (from labels), ||mean_sum||, fused cosine scale.
__global__ void k_msum(const float* __restrict__ labels) {
    const int tid = threadIdx.x;
    const int lane = tid & 31, wid = tid >> 5;
    float n0 = 0.f, msq = 0.f;
    for (int i = tid; i < B_SZ; i += 256) n0 += mask0_of(labels, i);
    for (int i = tid; i < D_SZ; i += 256) { float v = g_msum[i]; msq += v * v; }
    n0 = warpReduce(n0);
    msq = warpReduce(msq);
    __shared__ float s0[8], s1[8];
    if (lane == 0) { s0[wid] = n0; s1[wid] = msq; }
    __syncthreads();
    if (tid == 0) {
        float a = 0.f, b = 0.f;
        #pragma unroll
        for (int i = 0; i < 8; i++) { a += s0[i]; b += s1[i]; }
        float n0max = fmaxf(a, 1.f);
        // mean_vec = msum / n0max; m_norm = max(||mean_vec||, EPS)
        float mnorm = fmaxf(sqrtf(b) / n0max, EPS);
        g_scale = 1.f / (n0max * mnorm);
        g_n0f = a;
        g_n1f = (float)B_SZ - a;
    }
}

// Pass 2: 2 rows per warp, columns streamed BACKWARD (reverse of pass1's
// direction) to harvest L2 residue instead of cyclically evicting it.
// 512 blocks x 8 warps x 2 rows = 8192 rows. Mean staged in smem, shared
// between the two rows (halves LDS traffic, 16 LDGs in flight per thread).
__global__ void __launch_bounds__(256) k_pass2(const float* __restrict__ datas,
                                               const float* __restrict__ labels) {
    const int tid  = threadIdx.x;
    const int lane = tid & 31, wid = tid >> 5;
    __shared__ float4 sm4[D_SZ / 4];
    __shared__ float ssim[8], sdif[8];
    {
        const float4* gm4 = reinterpret_cast<const float4*>(g_msum);
        for (int i = tid; i < D_SZ / 4; i += 256) sm4[i] = gm4[i];
    }
    __syncthreads();

    const int r0 = blockIdx.x * 16 + wid * 2;
    const int r1 = r0 + 1;
    const float4* p0 = reinterpret_cast<const float4*>(datas + (size_t)r0 * D_SZ);
    const float4* p1 = reinterpret_cast<const float4*>(datas + (size_t)r1 * D_SZ);

    float dot0 = 0.f, ss0 = 0.f, dot1 = 0.f, ss1 = 0.f;
    #pragma unroll 8
    for (int ii = 0; ii < D_SZ / 4 / 32; ii++) {
        const int i = (D_SZ / 4 / 32 - 1) - ii;     // backward
        const int idx = lane + 32 * i;
        float4 v0 = p0[idx];
        float4 v1 = p1[idx];
        float4 w  = sm4[idx];
        dot0 += v0.x * w.x + v0.y * w.y + v0.z * w.z + v0.w * w.w;
        ss0  += v0.x * v0.x + v0.y * v0.y + v0.z * v0.z + v0.w * v0.w;
        dot1 += v1.x * w.x + v1.y * w.y + v1.z * w.z + v1.w * w.w;
        ss1  += v1.x * v1.x + v1.y * v1.y + v1.z * v1.z + v1.w * v1.w;
    }
    dot0 = warpReduce(dot0);
    ss0  = warpReduce(ss0);
    dot1 = warpReduce(dot1);
    ss1  = warpReduce(ss1);

    if (lane == 0) {
        const float scale = g_scale;
        float ac0 = fabsf(dot0 * scale / fmaxf(sqrtf(ss0), EPS));
        float ac1 = fabsf(dot1 * scale / fmaxf(sqrtf(ss1), EPS));
        float m0 = mask0_of(labels, r0);
        float m1 = mask0_of(labels, r1);
        ssim[wid] = m0 * (1.f - ac0) + m1 * (1.f - ac1);
        sdif[wid] = (1.f - m0) * ac0 + (1.f - m1) * ac1;
    }
    __syncthreads();
    if (tid == 0) {
        float a = 0.f, b = 0.f;
        #pragma unroll
        for (int i = 0; i < 8; i++) { a += ssim[i]; b += sdif[i]; }
        atomicAdd(&g_sim, a);
        atomicAdd(&g_dif, b);
    }
}

// Finalize: write outputs with edge-case guards, then restore all scratch
// accumulators to zero for the next graph replay.
__global__ void k_final(float* __restrict__ out) {
    int i = blockIdx.x * blockDim.x + threadIdx.x;
    if (i == 0) {
        float n0 = g_n0f, n1 = g_n1f;
        float sim = (n0 > 0.f) ? g_sim / fmaxf(n0, 1.f) : 0.f;
        float dif = (n0 > 0.f && n1 > 0.f) ? g_dif / fmaxf(n1, 1.f) : 0.f;
        out[0] = sim + dif;  // total_loss
        out[1] = sim;        // sim_loss
        out[2] = dif;        // differ_loss
        g_sim = 0.f;
        g_dif = 0.f;
    }
    if (i < D_SZ) g_msum[i] = 0.f;
}

extern "C" void kernel_launch(void* const* d_in, const int* in_sizes, int n_in,
                              void* d_out, int out_size) {
    // Identify labels (smaller tensor) vs datas by size.
    const float* labels = (const float*)d_in[0];
    const float* datas  = (const float*)d_in[1];
    if (n_in >= 2 && in_sizes[0] > in_sizes[1]) {
        labels = (const float*)d_in[1];
        datas  = (const float*)d_in[0];
    }

    k_pass1<<<4 * (B_SZ / ROWS1), 256>>>(datas, labels);   // 512 blocks
    k_msum<<<1, 256>>>(labels);
    k_pass2<<<B_SZ / 16, 256>>>(datas, labels);            // 512 blocks
    k_final<<<D_SZ / 256, 256>>>((float*)d_out);
}